// round 16
// baseline (speedup 1.0000x reference)
#include <cuda_runtime.h>
#include <cuda_bf16.h>
#include <math.h>

#define B_  32
#define T_  512
#define D_  1024
#define UN_ 1024
#define NG_ 3072
#define M_  (B_*T_)
#define NBLK 128

typedef unsigned long long ull;
typedef unsigned int u32;

// ---------------- cp.async helpers ----------------
__device__ __forceinline__ unsigned sptr(const void* p) {
    return (unsigned)__cvta_generic_to_shared(p);
}
#define CPA16(s, g)  asm volatile("cp.async.cg.shared.global [%0], [%1], 16;" :: "r"(s), "l"(g))
#define CPCOMMIT()   asm volatile("cp.async.commit_group;")
#define CPWAIT1()    asm volatile("cp.async.wait_group 1;")
#define CPWAIT0()    asm volatile("cp.async.wait_group 0;")

// ---------------- bf16 helpers ----------------
__device__ __forceinline__ unsigned short bfu(float v) {
    __nv_bfloat16 b = __float2bfloat16(v);
    return *(unsigned short*)&b;
}
__device__ __forceinline__ float ubf(unsigned short u) {
    return __bfloat162float(*(__nv_bfloat16*)&u);
}

// ---------------- mma.sync bf16 ----------------
#define MMA16816(c, a, b0, b1)                                              \
    asm("mma.sync.aligned.m16n8k16.row.col.f32.bf16.bf16.f32 "              \
        "{%0,%1,%2,%3}, {%4,%5,%6,%7}, {%8,%9}, {%0,%1,%2,%3};"             \
        : "+f"((c)[0]), "+f"((c)[1]), "+f"((c)[2]), "+f"((c)[3])            \
        : "r"((a)[0]), "r"((a)[1]), "r"((a)[2]), "r"((a)[3]),               \
          "r"(b0), "r"(b1))

// ---------------- device scratch ----------------
__device__ __align__(16) float g_xpt[(size_t)T_ * NG_ * B_];  // [t][col][b], bias folded
__device__ __align__(16) float g_bsum[NG_];
__device__ __align__(16) float g_hTf[2][UN_ * B_];            // fp32 [u][b] (hown init + final hT)
__device__ __align__(128) unsigned g_s1;
__device__ __align__(128) unsigned g_s2;
// bf16 split state, [b][u] layout (A row-major for MMA)
__device__ __align__(16) __nv_bfloat16 g_hbH[2][B_ * UN_];
__device__ __align__(16) __nv_bfloat16 g_hbL[2][B_ * UN_];
__device__ __align__(16) __nv_bfloat16 g_rbH[B_ * UN_];
__device__ __align__(16) __nv_bfloat16 g_rbL[B_ * UN_];
// bf16 split GEMM operands
__device__ __align__(16) __nv_bfloat16 g_xh[(size_t)M_ * D_];
__device__ __align__(16) __nv_bfloat16 g_xl[(size_t)M_ * D_];
__device__ __align__(16) __nv_bfloat16 g_Wht[(size_t)NG_ * D_];  // [n][k]
__device__ __align__(16) __nv_bfloat16 g_Wlt[(size_t)NG_ * D_];  // [n][k]

// ---------------- prep ----------------
__global__ void __launch_bounds__(256) k_prep(const float* __restrict__ b,
                                              const float* __restrict__ h0) {
    const int tid = threadIdx.x, bid = blockIdx.x;
    if (bid < 12) {
        int c = bid * 256 + tid;
        float acc = 0.f;
        for (int k = 0; k < D_; k++) acc += b[(size_t)k * NG_ + c];
        g_bsum[c] = acc;
    }
    int i = bid * 256 + tid;            // 0..32767
    int u = i >> 5, bb = i & 31;
    float v = h0[bb * UN_ + u];
    g_hTf[0][i] = v;
    unsigned short hi = bfu(v);
    g_hbH[0][bb * UN_ + u] = *(__nv_bfloat16*)&hi;
    unsigned short lo = bfu(v - ubf(hi));
    g_hbL[0][bb * UN_ + u] = *(__nv_bfloat16*)&lo;
    if (bid == 0 && tid == 0) { g_s1 = 0u; g_s2 = 0u; }
}

// ---------------- split x and W ----------------
__global__ void __launch_bounds__(256) k_split(const float* __restrict__ x,
                                               const float* __restrict__ W) {
    __shared__ float tile[32][33];
    if (blockIdx.x < 16384) {
        size_t i = ((size_t)blockIdx.x * 256 + threadIdx.x) * 4;
        float4 v = *(const float4*)(x + i);
        unsigned short h0 = bfu(v.x), h1 = bfu(v.y), h2 = bfu(v.z), h3 = bfu(v.w);
        unsigned short l0 = bfu(v.x - ubf(h0)), l1 = bfu(v.y - ubf(h1));
        unsigned short l2 = bfu(v.z - ubf(h2)), l3 = bfu(v.w - ubf(h3));
        ull hv = (ull)h0 | ((ull)h1 << 16) | ((ull)h2 << 32) | ((ull)h3 << 48);
        ull lv = (ull)l0 | ((ull)l1 << 16) | ((ull)l2 << 32) | ((ull)l3 << 48);
        *(ull*)(g_xh + i) = hv;
        *(ull*)(g_xl + i) = lv;
    } else {
        int w = blockIdx.x - 16384;
        const int n0 = (w % 96) * 32;
        const int k0 = (w / 96) * 32;
        const int tx = threadIdx.x & 31, ty = threadIdx.x >> 5;
#pragma unroll
        for (int j = 0; j < 32; j += 8)
            tile[ty + j][tx] = W[(size_t)(k0 + ty + j) * NG_ + n0 + tx];
        __syncthreads();
#pragma unroll
        for (int j = 0; j < 32; j += 8) {
            float v = tile[tx][ty + j];
            unsigned short h = bfu(v);
            g_Wht[(size_t)(n0 + ty + j) * D_ + k0 + tx] = *(__nv_bfloat16*)&h;
            unsigned short l = bfu(v - ubf(h));
            g_Wlt[(size_t)(n0 + ty + j) * D_ + k0 + tx] = *(__nv_bfloat16*)&l;
        }
    }
}

// ---------------- tensor-core GEMM with fused xpt epilogue (R14, unchanged) ----------------
#define GSM_BUF 20480
__global__ void __launch_bounds__(256, 1) k_gemm_mma() {
    extern __shared__ __nv_bfloat16 smb[];
    const int tid = threadIdx.x;
    const int t0 = blockIdx.y * 4;
    const int n0 = blockIdx.x * 128;
    const int w = tid >> 5, lane = tid & 31;
    const int wm = (w & 3) * 32, wn = (w >> 2) * 64;
    const int g = lane >> 2, t4 = lane & 3;

    float C[2][8][4];
#pragma unroll
    for (int mi = 0; mi < 2; mi++)
#pragma unroll
        for (int f = 0; f < 8; f++)
#pragma unroll
            for (int e = 0; e < 4; e++) C[mi][f][e] = 0.f;

    const int sr = tid >> 1;
    const int sc = (tid & 1) * 16;
    const int arow = (sr & 31) * T_ + t0 + (sr >> 5);

    auto stage = [&](int kc, int buf) {
        __nv_bfloat16* dst = smb + buf * GSM_BUF;
        const size_t ga = (size_t)arow * D_ + kc * 32 + sc;
        const size_t gb = (size_t)(n0 + sr) * D_ + kc * 32 + sc;
        unsigned d0 = sptr(dst + sr * 40 + sc);
        CPA16(d0,              g_xh + ga);
        CPA16(d0 + 16,         g_xh + ga + 8);
        CPA16(d0 + 10240,      g_xl + ga);
        CPA16(d0 + 10240 + 16, g_xl + ga + 8);
        CPA16(d0 + 20480,      g_Wht + gb);
        CPA16(d0 + 20480 + 16, g_Wht + gb + 8);
        CPA16(d0 + 30720,      g_Wlt + gb);
        CPA16(d0 + 30720 + 16, g_Wlt + gb + 8);
    };

    stage(0, 0); CPCOMMIT();

    for (int kc = 0; kc < 32; kc++) {
        if (kc < 31) { stage(kc + 1, (kc + 1) & 1); CPCOMMIT(); }
        if (kc < 31) CPWAIT1(); else CPWAIT0();
        __syncthreads();

        const u32* S  = (const u32*)(smb + (kc & 1) * GSM_BUF);
        const u32* AL = S + 2560;
        const u32* BH = S + 5120;
        const u32* BL = S + 7680;

#pragma unroll
        for (int ks = 0; ks < 2; ks++) {
            const int cb = ks * 8 + t4;
            u32 ah[2][4], al[2][4];
#pragma unroll
            for (int mi = 0; mi < 2; mi++) {
                int r = wm + mi * 16 + g;
                ah[mi][0] = S[r * 20 + cb];
                ah[mi][1] = S[(r + 8) * 20 + cb];
                ah[mi][2] = S[r * 20 + cb + 4];
                ah[mi][3] = S[(r + 8) * 20 + cb + 4];
                al[mi][0] = AL[r * 20 + cb];
                al[mi][1] = AL[(r + 8) * 20 + cb];
                al[mi][2] = AL[r * 20 + cb + 4];
                al[mi][3] = AL[(r + 8) * 20 + cb + 4];
            }
#pragma unroll
            for (int f = 0; f < 8; f++) {
                int n = wn + f * 8 + g;
                u32 bh0 = BH[n * 20 + cb], bh1 = BH[n * 20 + cb + 4];
                u32 bl0 = BL[n * 20 + cb], bl1 = BL[n * 20 + cb + 4];
#pragma unroll
                for (int mi = 0; mi < 2; mi++) {
                    MMA16816(C[mi][f], ah[mi], bh0, bh1);
                    MMA16816(C[mi][f], al[mi], bh0, bh1);
                    MMA16816(C[mi][f], ah[mi], bl0, bl1);
                }
            }
        }
        __syncthreads();
    }

    float* sms = (float*)smb;
#pragma unroll
    for (int mi = 0; mi < 2; mi++)
#pragma unroll
        for (int f = 0; f < 8; f++) {
            int r = wm + mi * 16 + g;
            int c = wn + f * 8 + t4 * 2;
            *(float2*)&sms[r * 130 + c]       = make_float2(C[mi][f][0], C[mi][f][1]);
            *(float2*)&sms[(r + 8) * 130 + c] = make_float2(C[mi][f][2], C[mi][f][3]);
        }
    __syncthreads();
#pragma unroll
    for (int j = 0; j < 16; j++) {
        int L  = j * 1024 + tid * 4;
        int tp = L >> 12;
        int c  = (L >> 5) & 127;
        int b  = L & 31;
        int r  = tp * 32 + b;
        float bias = g_bsum[n0 + c];
        float4 o;
        o.x = sms[(r + 0) * 130 + c] + bias;
        o.y = sms[(r + 1) * 130 + c] + bias;
        o.z = sms[(r + 2) * 130 + c] + bias;
        o.w = sms[(r + 3) * 130 + c] + bias;
        *(float4*)&g_xpt[((size_t)(t0 + tp) * NG_ + n0 + c) * B_ + b] = o;
    }
}

// ---------------- split sync (R15) ----------------
__device__ __forceinline__ void g_arrive(unsigned* cnt) {
    __syncthreads();
    if (threadIdx.x == 0) atomicAdd(cnt, 1u);
}
__device__ __forceinline__ void g_wait(unsigned* cnt, unsigned tgt) {
    if (threadIdx.x == 0) {
        int spins = 0;
        while (*((volatile unsigned*)cnt) < tgt) {
            if (++spins > 8) __nanosleep(64);
        }
        __threadfence();
    }
    __syncthreads();
}

// ---------------- persistent GRU: tensor-core passes ----------------
// smem u32 map:
//  UF   [6 gate-terms][8 u][516]          : 0      .. 24768
//  HST  6 slots x (hi 32x68 | lo 32x68)   : 24768  .. 50880
//  RED  2048 f32                          : 50880  .. 52928
//  XPS  768 | ZS 256 | HOWN 256           : 52928  .. 54208
#define UF0    0
#define HSTB   24768
#define REDO   50880
#define XPSO   52928
#define ZSO    53696
#define HOWNO  53952
#define SMTOT  54208

__global__ void __launch_bounds__(512, 1) k_gru(const float* __restrict__ U,
                                                float* __restrict__ out) {
    extern __shared__ u32 smU[];
    float* smF  = (float*)smU;
    float* red  = smF + REDO;
    float* xps  = smF + XPSO;           // [0:256)=xz [256:512)=xr [512:768)=xh
    float* z_s  = smF + ZSO;
    float* hown = smF + HOWNO;

    const int bid = blockIdx.x, tid = threadIdx.x;
    const int u0 = bid * 8;
    const int w = tid >> 5, lane = tid & 31;
    const int mt = w & 1, ks = w >> 1;
    const int g = lane >> 2, t4 = lane & 3;

    // ---- U fragments: [gate*2+term][u][kk], packed bf16 pairs ----
    for (int i = tid; i < 3 * 8 * 512; i += 512) {
        int gate = i >> 12;
        int rem  = i & 4095;
        int u    = rem >> 9;
        int kk   = rem & 511;
        int col  = gate * UN_ + u0 + u;
        float v0 = U[(size_t)(2 * kk)     * NG_ + col];
        float v1 = U[(size_t)(2 * kk + 1) * NG_ + col];
        unsigned short h0 = bfu(v0), h1 = bfu(v1);
        unsigned short l0 = bfu(v0 - ubf(h0)), l1 = bfu(v1 - ubf(h1));
        smU[UF0 + (gate * 2)     * 4128 + u * 516 + kk] = (u32)h0 | ((u32)h1 << 16);
        smU[UF0 + (gate * 2 + 1) * 4128 + u * 516 + kk] = (u32)l0 | ((u32)l1 << 16);
    }
    if (tid < 256) hown[tid] = g_hTf[0][u0 * B_ + tid];
    __syncthreads();

    const int sb = tid >> 4, sgi = tid & 15;   // staging: row b, 16B segment

    auto stage = [&](int c, const __nv_bfloat16* srcH, const __nv_bfloat16* srcL) {
        u32* dst = smU + HSTB + (c % 6) * 4352 + sb * 68 + sgi * 4;
        const __nv_bfloat16* sH = srcH + sb * UN_ + c * 128 + sgi * 8;
        const __nv_bfloat16* sL = srcL + sb * UN_ + c * 128 + sgi * 8;
        CPA16(sptr(dst), sH);
        CPA16(sptr(dst + 2176), sL);
    };

    // one chunk's 3-term MMA contribution (per warp)
#define CHUNK_MMA(gthi, cix)                                                  \
    {                                                                         \
        const u32* sl = smU + HSTB + ((cix) % 6) * 4352;                      \
        const int ia = (mt * 16 + g) * 68 + ks * 8 + t4;                      \
        u32 ah[4], al[4];                                                     \
        ah[0] = sl[ia];        ah[1] = sl[ia + 544];                          \
        ah[2] = sl[ia + 4];    ah[3] = sl[ia + 548];                          \
        al[0] = sl[ia + 2176]; al[1] = sl[ia + 2720];                         \
        al[2] = sl[ia + 2180]; al[3] = sl[ia + 2724];                         \
        const int ib = UF0 + (gthi) * 4128 + g * 516 + (cix) * 64 + ks * 8 + t4; \
        u32 bh0 = smU[ib], bh1 = smU[ib + 4];                                 \
        u32 bl0 = smU[ib + 4128], bl1 = smU[ib + 4128 + 4];                   \
        MMA16816(C, ah, bh0, bh1);                                            \
        MMA16816(C, al, bh0, bh1);                                            \
        MMA16816(C, ah, bl0, bl1);                                            \
    }

    // reduce 16 warp-frags -> per-thread (b, n) value for tid<256
#define FRAG_REDUCE(valout)                                                   \
    *(float4*)&red[w * 128 + lane * 4] = *(float4*)C;                         \
    __syncthreads();                                                          \
    float valout = 0.f;                                                       \
    int bb = 0, nn = 0;                                                       \
    if (tid < 256) {                                                          \
        bb = tid >> 3; nn = tid & 7;                                          \
        int mtt = bb >> 4, rt = bb & 15;                                      \
        int ln = (rt & 7) * 4 + (nn >> 1);                                    \
        int rg = ((rt >> 3) & 1) * 2 + (nn & 1);                              \
        _Pragma("unroll")                                                     \
        for (int j = 0; j < 8; j++)                                           \
            valout += red[(2 * j + mtt) * 128 + ln * 4 + rg];                 \
    }

    for (int t = 0; t < T_; t++) {
        const __nv_bfloat16* hH = g_hbH[t & 1];
        const __nv_bfloat16* hL = g_hbL[t & 1];
        const float* xpt_t = g_xpt + (size_t)t * NG_ * B_;
        float C[4];

        // ========== pass 1: r -> rh (global, split bf16) ==========
        stage(0, hH, hL);
        stage(1, hH, hL);
        if (tid < 64)
            CPA16(sptr((u32*)&xps[tid * 4]), xpt_t + (size_t)u0 * B_ + tid * 4);
        else if (tid < 128)
            CPA16(sptr((u32*)&xps[tid * 4]), xpt_t + (size_t)(UN_ + u0) * B_ + (tid - 64) * 4);
        CPCOMMIT();                                       // G0: c0,c1,xz,xr
        stage(2, hH, hL); stage(3, hH, hL); CPCOMMIT();   // G1

        C[0] = C[1] = C[2] = C[3] = 0.f;
        CPWAIT1(); __syncthreads();
        stage(4, hH, hL); stage(5, hH, hL); CPCOMMIT();   // G2
        CHUNK_MMA(2, 0) CHUNK_MMA(2, 1)
        CPWAIT1(); __syncthreads();
        stage(6, hH, hL); stage(7, hH, hL); CPCOMMIT();   // G3
        CHUNK_MMA(2, 2) CHUNK_MMA(2, 3)
        CPWAIT1(); __syncthreads();
        CHUNK_MMA(2, 4) CHUNK_MMA(2, 5)
        CPWAIT0(); __syncthreads();
        CHUNK_MMA(2, 6) CHUNK_MMA(2, 7)
        __syncthreads();

        {
            FRAG_REDUCE(val)
            if (tid < 256) {
                float rs = val + xps[256 + nn * 32 + bb];
                float r  = 1.f / (1.f + __expf(-rs));
                float rh = r * hown[nn * 32 + bb];
                unsigned short hi = bfu(rh);
                g_rbH[bb * UN_ + u0 + nn] = *(__nv_bfloat16*)&hi;
                unsigned short lo = bfu(rh - ubf(hi));
                g_rbL[bb * UN_ + u0 + nn] = *(__nv_bfloat16*)&lo;
                __threadfence();
            }
        }
        g_arrive(&g_s1);

        // ========== pass 2: z (local) — reuses resident h chunks ==========
        C[0] = C[1] = C[2] = C[3] = 0.f;
        CHUNK_MMA(0, 6) CHUNK_MMA(0, 7)
        __syncthreads();
        stage(0, hH, hL); stage(1, hH, hL); CPCOMMIT();
        CHUNK_MMA(0, 2) CHUNK_MMA(0, 3) CHUNK_MMA(0, 4) CHUNK_MMA(0, 5)
        CPWAIT0(); __syncthreads();
        CHUNK_MMA(0, 0) CHUNK_MMA(0, 1)
        __syncthreads();

        {
            FRAG_REDUCE(val)
            if (tid < 256) {
                float zs = val + xps[nn * 32 + bb];
                z_s[nn * 32 + bb] = 1.f / (1.f + __expf(-zs));
            }
        }
        g_wait(&g_s1, (unsigned)NBLK * (t + 1));

        // ========== pass 3: hcand + hn ==========
        stage(0, g_rbH, g_rbL);
        stage(1, g_rbH, g_rbL);
        if (tid < 64)
            CPA16(sptr((u32*)&xps[512 + tid * 4]),
                  xpt_t + (size_t)(2 * UN_ + u0) * B_ + tid * 4);
        CPCOMMIT();                                       // G0
        stage(2, g_rbH, g_rbL); stage(3, g_rbH, g_rbL); CPCOMMIT();   // G1

        C[0] = C[1] = C[2] = C[3] = 0.f;
        CPWAIT1(); __syncthreads();
        stage(4, g_rbH, g_rbL); stage(5, g_rbH, g_rbL); CPCOMMIT();   // G2
        CHUNK_MMA(4, 0) CHUNK_MMA(4, 1)
        CPWAIT1(); __syncthreads();
        stage(6, g_rbH, g_rbL); stage(7, g_rbH, g_rbL); CPCOMMIT();   // G3
        CHUNK_MMA(4, 2) CHUNK_MMA(4, 3)
        CPWAIT1(); __syncthreads();
        CHUNK_MMA(4, 4) CHUNK_MMA(4, 5)
        CPWAIT0(); __syncthreads();
        CHUNK_MMA(4, 6) CHUNK_MMA(4, 7)
        __syncthreads();

        {
            FRAG_REDUCE(val)
            if (tid < 256) {
                float hc = tanhf(val + xps[512 + nn * 32 + bb]);
                float z  = z_s[nn * 32 + bb];
                float ho = hown[nn * 32 + bb];
                float hn = z * ho + (1.f - z) * hc;
                hown[nn * 32 + bb] = hn;
                out[((size_t)bb * T_ + t) * UN_ + u0 + nn] = hn;
                unsigned short hi = bfu(hn);
                g_hbH[(t + 1) & 1][bb * UN_ + u0 + nn] = *(__nv_bfloat16*)&hi;
                unsigned short lo = bfu(hn - ubf(hi));
                g_hbL[(t + 1) & 1][bb * UN_ + u0 + nn] = *(__nv_bfloat16*)&lo;
                if (t == T_ - 1)
                    g_hTf[0][(u0 + nn) * B_ + bb] = hn;
                __threadfence();
            }
        }
        g_arrive(&g_s2);
        g_wait(&g_s2, (unsigned)NBLK * (t + 1));
    }

    // final hidden state hT (fp32 buffer 0)
    if (bid < 64) {
        int i = bid * 512 + tid;          // i = u*32 + b
        int u = i >> 5, b = i & 31;
        out[(size_t)M_ * UN_ + (size_t)b * UN_ + u] = __ldcg(&g_hTf[0][i]);
    }
#undef CHUNK_MMA
#undef FRAG_REDUCE
}

// ---------------- launcher ----------------
extern "C" void kernel_launch(void* const* d_in, const int* in_sizes, int n_in,
                              void* d_out, int out_size) {
    const float* x  = (const float*)d_in[0];
    const float* W  = (const float*)d_in[1];
    const float* U  = (const float*)d_in[2];
    const float* b  = (const float*)d_in[3];
    const float* h0 = (const float*)d_in[4];
    float* out = (float*)d_out;

    static bool attr_done = false;
    if (!attr_done) {
        cudaFuncSetAttribute(k_gru, cudaFuncAttributeMaxDynamicSharedMemorySize,
                             SMTOT * 4);
        cudaFuncSetAttribute(k_gemm_mma, cudaFuncAttributeMaxDynamicSharedMemorySize,
                             2 * GSM_BUF * sizeof(__nv_bfloat16));
        attr_done = true;
    }

    k_prep<<<NBLK, 256>>>(b, h0);                        // launch 1
    k_split<<<16384 + 3072, 256>>>(x, W);                // launch 2
    {
        dim3 grid(NG_ / 128, M_ / 128);
        k_gemm_mma<<<grid, 256, 2 * GSM_BUF * sizeof(__nv_bfloat16)>>>();  // launch 3
    }
    k_gru<<<NBLK, 512, SMTOT * 4>>>(U, out);             // launch 4
}

// round 17
// speedup vs baseline: 1.0370x; 1.0370x over previous
#include <cuda_runtime.h>
#include <cuda_bf16.h>
#include <math.h>

#define B_  32
#define T_  512
#define D_  1024
#define UN_ 1024
#define NG_ 3072
#define M_  (B_*T_)
#define NBLK 128

typedef unsigned long long ull;
typedef unsigned int u32;

// ---------------- cp.async helpers ----------------
__device__ __forceinline__ unsigned sptr(const void* p) {
    return (unsigned)__cvta_generic_to_shared(p);
}
#define CPA16(s, g)  asm volatile("cp.async.cg.shared.global [%0], [%1], 16;" :: "r"(s), "l"(g))
#define CPCOMMIT()   asm volatile("cp.async.commit_group;")
#define CPWAIT1()    asm volatile("cp.async.wait_group 1;")
#define CPWAIT0()    asm volatile("cp.async.wait_group 0;")

// ---------------- bf16 helpers ----------------
__device__ __forceinline__ unsigned short bfu(float v) {
    __nv_bfloat16 b = __float2bfloat16(v);
    return *(unsigned short*)&b;
}
__device__ __forceinline__ float ubf(unsigned short u) {
    return __bfloat162float(*(__nv_bfloat16*)&u);
}

// ---------------- mma.sync bf16 ----------------
#define MMA16816(c, a, b0, b1)                                              \
    asm("mma.sync.aligned.m16n8k16.row.col.f32.bf16.bf16.f32 "              \
        "{%0,%1,%2,%3}, {%4,%5,%6,%7}, {%8,%9}, {%0,%1,%2,%3};"             \
        : "+f"((c)[0]), "+f"((c)[1]), "+f"((c)[2]), "+f"((c)[3])            \
        : "r"((a)[0]), "r"((a)[1]), "r"((a)[2]), "r"((a)[3]),               \
          "r"(b0), "r"(b1))

// ---------------- device scratch ----------------
__device__ __align__(16) float g_xpt[(size_t)T_ * NG_ * B_];  // [t][col][b], bias folded
__device__ __align__(16) float g_bsum[NG_];
__device__ __align__(16) float g_hTf[2][UN_ * B_];            // fp32 [u][b]
__device__ __align__(128) unsigned g_s1;
__device__ __align__(128) unsigned g_s2;
// bf16 split state, [b][u] layout
__device__ __align__(16) __nv_bfloat16 g_hbH[2][B_ * UN_];
__device__ __align__(16) __nv_bfloat16 g_hbL[2][B_ * UN_];
__device__ __align__(16) __nv_bfloat16 g_rbH[B_ * UN_];
__device__ __align__(16) __nv_bfloat16 g_rbL[B_ * UN_];
// bf16 split GEMM operands
__device__ __align__(16) __nv_bfloat16 g_xh[(size_t)M_ * D_];
__device__ __align__(16) __nv_bfloat16 g_xl[(size_t)M_ * D_];
__device__ __align__(16) __nv_bfloat16 g_Wht[(size_t)NG_ * D_];  // [n][k]
__device__ __align__(16) __nv_bfloat16 g_Wlt[(size_t)NG_ * D_];  // [n][k]

// ---------------- prep ----------------
__global__ void __launch_bounds__(256) k_prep(const float* __restrict__ b,
                                              const float* __restrict__ h0) {
    const int tid = threadIdx.x, bid = blockIdx.x;
    if (bid < 12) {
        int c = bid * 256 + tid;
        float acc = 0.f;
        for (int k = 0; k < D_; k++) acc += b[(size_t)k * NG_ + c];
        g_bsum[c] = acc;
    }
    int i = bid * 256 + tid;
    int u = i >> 5, bb = i & 31;
    float v = h0[bb * UN_ + u];
    g_hTf[0][i] = v;
    unsigned short hi = bfu(v);
    g_hbH[0][bb * UN_ + u] = *(__nv_bfloat16*)&hi;
    unsigned short lo = bfu(v - ubf(hi));
    g_hbL[0][bb * UN_ + u] = *(__nv_bfloat16*)&lo;
    if (bid == 0 && tid == 0) { g_s1 = 0u; g_s2 = 0u; }
}

// ---------------- split x and W ----------------
__global__ void __launch_bounds__(256) k_split(const float* __restrict__ x,
                                               const float* __restrict__ W) {
    __shared__ float tile[32][33];
    if (blockIdx.x < 16384) {
        size_t i = ((size_t)blockIdx.x * 256 + threadIdx.x) * 4;
        float4 v = *(const float4*)(x + i);
        unsigned short h0 = bfu(v.x), h1 = bfu(v.y), h2 = bfu(v.z), h3 = bfu(v.w);
        unsigned short l0 = bfu(v.x - ubf(h0)), l1 = bfu(v.y - ubf(h1));
        unsigned short l2 = bfu(v.z - ubf(h2)), l3 = bfu(v.w - ubf(h3));
        ull hv = (ull)h0 | ((ull)h1 << 16) | ((ull)h2 << 32) | ((ull)h3 << 48);
        ull lv = (ull)l0 | ((ull)l1 << 16) | ((ull)l2 << 32) | ((ull)l3 << 48);
        *(ull*)(g_xh + i) = hv;
        *(ull*)(g_xl + i) = lv;
    } else {
        int w = blockIdx.x - 16384;
        const int n0 = (w % 96) * 32;
        const int k0 = (w / 96) * 32;
        const int tx = threadIdx.x & 31, ty = threadIdx.x >> 5;
#pragma unroll
        for (int j = 0; j < 32; j += 8)
            tile[ty + j][tx] = W[(size_t)(k0 + ty + j) * NG_ + n0 + tx];
        __syncthreads();
#pragma unroll
        for (int j = 0; j < 32; j += 8) {
            float v = tile[tx][ty + j];
            unsigned short h = bfu(v);
            g_Wht[(size_t)(n0 + ty + j) * D_ + k0 + tx] = *(__nv_bfloat16*)&h;
            unsigned short l = bfu(v - ubf(h));
            g_Wlt[(size_t)(n0 + ty + j) * D_ + k0 + tx] = *(__nv_bfloat16*)&l;
        }
    }
}

// ---------------- tensor-core GEMM with fused xpt epilogue (R14, unchanged) ----------------
#define GSM_BUF 20480
__global__ void __launch_bounds__(256, 1) k_gemm_mma() {
    extern __shared__ __nv_bfloat16 smb[];
    const int tid = threadIdx.x;
    const int t0 = blockIdx.y * 4;
    const int n0 = blockIdx.x * 128;
    const int w = tid >> 5, lane = tid & 31;
    const int wm = (w & 3) * 32, wn = (w >> 2) * 64;
    const int g = lane >> 2, t4 = lane & 3;

    float C[2][8][4];
#pragma unroll
    for (int mi = 0; mi < 2; mi++)
#pragma unroll
        for (int f = 0; f < 8; f++)
#pragma unroll
            for (int e = 0; e < 4; e++) C[mi][f][e] = 0.f;

    const int sr = tid >> 1;
    const int sc = (tid & 1) * 16;
    const int arow = (sr & 31) * T_ + t0 + (sr >> 5);

    auto stage = [&](int kc, int buf) {
        __nv_bfloat16* dst = smb + buf * GSM_BUF;
        const size_t ga = (size_t)arow * D_ + kc * 32 + sc;
        const size_t gb = (size_t)(n0 + sr) * D_ + kc * 32 + sc;
        unsigned d0 = sptr(dst + sr * 40 + sc);
        CPA16(d0,              g_xh + ga);
        CPA16(d0 + 16,         g_xh + ga + 8);
        CPA16(d0 + 10240,      g_xl + ga);
        CPA16(d0 + 10240 + 16, g_xl + ga + 8);
        CPA16(d0 + 20480,      g_Wht + gb);
        CPA16(d0 + 20480 + 16, g_Wht + gb + 8);
        CPA16(d0 + 30720,      g_Wlt + gb);
        CPA16(d0 + 30720 + 16, g_Wlt + gb + 8);
    };

    stage(0, 0); CPCOMMIT();

    for (int kc = 0; kc < 32; kc++) {
        if (kc < 31) { stage(kc + 1, (kc + 1) & 1); CPCOMMIT(); }
        if (kc < 31) CPWAIT1(); else CPWAIT0();
        __syncthreads();

        const u32* S  = (const u32*)(smb + (kc & 1) * GSM_BUF);
        const u32* AL = S + 2560;
        const u32* BH = S + 5120;
        const u32* BL = S + 7680;

#pragma unroll
        for (int ks = 0; ks < 2; ks++) {
            const int cb = ks * 8 + t4;
            u32 ah[2][4], al[2][4];
#pragma unroll
            for (int mi = 0; mi < 2; mi++) {
                int r = wm + mi * 16 + g;
                ah[mi][0] = S[r * 20 + cb];
                ah[mi][1] = S[(r + 8) * 20 + cb];
                ah[mi][2] = S[r * 20 + cb + 4];
                ah[mi][3] = S[(r + 8) * 20 + cb + 4];
                al[mi][0] = AL[r * 20 + cb];
                al[mi][1] = AL[(r + 8) * 20 + cb];
                al[mi][2] = AL[r * 20 + cb + 4];
                al[mi][3] = AL[(r + 8) * 20 + cb + 4];
            }
#pragma unroll
            for (int f = 0; f < 8; f++) {
                int n = wn + f * 8 + g;
                u32 bh0 = BH[n * 20 + cb], bh1 = BH[n * 20 + cb + 4];
                u32 bl0 = BL[n * 20 + cb], bl1 = BL[n * 20 + cb + 4];
#pragma unroll
                for (int mi = 0; mi < 2; mi++) {
                    MMA16816(C[mi][f], ah[mi], bh0, bh1);
                    MMA16816(C[mi][f], al[mi], bh0, bh1);
                    MMA16816(C[mi][f], ah[mi], bl0, bl1);
                }
            }
        }
        __syncthreads();
    }

    float* sms = (float*)smb;
#pragma unroll
    for (int mi = 0; mi < 2; mi++)
#pragma unroll
        for (int f = 0; f < 8; f++) {
            int r = wm + mi * 16 + g;
            int c = wn + f * 8 + t4 * 2;
            *(float2*)&sms[r * 130 + c]       = make_float2(C[mi][f][0], C[mi][f][1]);
            *(float2*)&sms[(r + 8) * 130 + c] = make_float2(C[mi][f][2], C[mi][f][3]);
        }
    __syncthreads();
#pragma unroll
    for (int j = 0; j < 16; j++) {
        int L  = j * 1024 + tid * 4;
        int tp = L >> 12;
        int c  = (L >> 5) & 127;
        int b  = L & 31;
        int r  = tp * 32 + b;
        float bias = g_bsum[n0 + c];
        float4 o;
        o.x = sms[(r + 0) * 130 + c] + bias;
        o.y = sms[(r + 1) * 130 + c] + bias;
        o.z = sms[(r + 2) * 130 + c] + bias;
        o.w = sms[(r + 3) * 130 + c] + bias;
        *(float4*)&g_xpt[((size_t)(t0 + tp) * NG_ + n0 + c) * B_ + b] = o;
    }
}

// ---------------- split sync ----------------
__device__ __forceinline__ void g_arrive(unsigned* cnt) {
    __syncthreads();
    if (threadIdx.x == 0) atomicAdd(cnt, 1u);
}
__device__ __forceinline__ void g_wait(unsigned* cnt, unsigned tgt) {
    if (threadIdx.x == 0) {
        int spins = 0;
        while (*((volatile unsigned*)cnt) < tgt) {
            if (++spins > 8) __nanosleep(64);
        }
        __threadfence();
    }
    __syncthreads();
}

// ---------------- persistent GRU: 2-pass tensor-core ----------------
// smem u32 map:
//  UF   [6 gate-terms][8 u][516]          : 0      .. 24768
//  HST  6 slots x (hi 32x68 | lo 32x68)   : 24768  .. 50880
//  RED  2048 f32                          : 50880  .. 52928
//  XPS  768 | ZS 256 | HOWN 256           : 52928  .. 54208
#define UF0    0
#define HSTB   24768
#define REDO   50880
#define XPSO   52928
#define ZSO    53696
#define HOWNO  53952
#define SMTOT  54208

__global__ void __launch_bounds__(512, 1) k_gru(const float* __restrict__ U,
                                                float* __restrict__ out) {
    extern __shared__ u32 smU[];
    float* smF  = (float*)smU;
    float* red  = smF + REDO;
    float* xps  = smF + XPSO;           // [0:256)=xz [256:512)=xr [512:768)=xh
    float* z_s  = smF + ZSO;
    float* hown = smF + HOWNO;

    const int bid = blockIdx.x, tid = threadIdx.x;
    const int u0 = bid * 8;
    const int w = tid >> 5, lane = tid & 31;
    const int mt = w & 1, ks = w >> 1;
    const int g = lane >> 2, t4 = lane & 3;

    // ---- U fragments: [gate*2+term][u][kk] ----
    for (int i = tid; i < 3 * 8 * 512; i += 512) {
        int gate = i >> 12;
        int rem  = i & 4095;
        int u    = rem >> 9;
        int kk   = rem & 511;
        int col  = gate * UN_ + u0 + u;
        float v0 = U[(size_t)(2 * kk)     * NG_ + col];
        float v1 = U[(size_t)(2 * kk + 1) * NG_ + col];
        unsigned short h0 = bfu(v0), h1 = bfu(v1);
        unsigned short l0 = bfu(v0 - ubf(h0)), l1 = bfu(v1 - ubf(h1));
        smU[UF0 + (gate * 2)     * 4128 + u * 516 + kk] = (u32)h0 | ((u32)h1 << 16);
        smU[UF0 + (gate * 2 + 1) * 4128 + u * 516 + kk] = (u32)l0 | ((u32)l1 << 16);
    }
    if (tid < 256) hown[tid] = g_hTf[0][u0 * B_ + tid];
    __syncthreads();

    const int sb = tid >> 4, sgi = tid & 15;

    auto stage = [&](int c, const __nv_bfloat16* srcH, const __nv_bfloat16* srcL) {
        u32* dst = smU + HSTB + (c % 6) * 4352 + sb * 68 + sgi * 4;
        const __nv_bfloat16* sH = srcH + sb * UN_ + c * 128 + sgi * 8;
        const __nv_bfloat16* sL = srcL + sb * UN_ + c * 128 + sgi * 8;
        CPA16(sptr(dst), sH);
        CPA16(sptr(dst + 2176), sL);
    };

    // dual-gate chunk: A-frags loaded once, z(terms 0,1) + r(terms 2,3)
#define CHUNK_ZR(cix)                                                         \
    {                                                                         \
        const u32* sl = smU + HSTB + ((cix) % 6) * 4352;                      \
        const int ia = (mt * 16 + g) * 68 + ks * 8 + t4;                      \
        u32 ah[4], al[4];                                                     \
        ah[0] = sl[ia];        ah[1] = sl[ia + 544];                          \
        ah[2] = sl[ia + 4];    ah[3] = sl[ia + 548];                          \
        al[0] = sl[ia + 2176]; al[1] = sl[ia + 2720];                         \
        al[2] = sl[ia + 2180]; al[3] = sl[ia + 2724];                         \
        const int ibz = UF0 + g * 516 + (cix) * 64 + ks * 8 + t4;             \
        u32 zh0 = smU[ibz], zh1 = smU[ibz + 4];                               \
        u32 zl0 = smU[ibz + 4128], zl1 = smU[ibz + 4132];                     \
        const int ibr = ibz + 2 * 4128;                                       \
        u32 rh0 = smU[ibr], rh1 = smU[ibr + 4];                               \
        u32 rl0 = smU[ibr + 4128], rl1 = smU[ibr + 4132];                     \
        MMA16816(Cr, ah, rh0, rh1);                                           \
        MMA16816(Cr, al, rh0, rh1);                                           \
        MMA16816(Cr, ah, rl0, rl1);                                           \
        MMA16816(Cz, ah, zh0, zh1);                                           \
        MMA16816(Cz, al, zh0, zh1);                                           \
        MMA16816(Cz, ah, zl0, zl1);                                           \
    }

    // single-gate chunk (pass B, gate terms 4,5)
#define CHUNK_H(cix)                                                          \
    {                                                                         \
        const u32* sl = smU + HSTB + ((cix) % 6) * 4352;                      \
        const int ia = (mt * 16 + g) * 68 + ks * 8 + t4;                      \
        u32 ah[4], al[4];                                                     \
        ah[0] = sl[ia];        ah[1] = sl[ia + 544];                          \
        ah[2] = sl[ia + 4];    ah[3] = sl[ia + 548];                          \
        al[0] = sl[ia + 2176]; al[1] = sl[ia + 2720];                         \
        al[2] = sl[ia + 2180]; al[3] = sl[ia + 2724];                         \
        const int ib = UF0 + 4 * 4128 + g * 516 + (cix) * 64 + ks * 8 + t4;   \
        u32 bh0 = smU[ib], bh1 = smU[ib + 4];                                 \
        u32 bl0 = smU[ib + 4128], bl1 = smU[ib + 4132];                       \
        MMA16816(Cr, ah, bh0, bh1);                                           \
        MMA16816(Cr, al, bh0, bh1);                                           \
        MMA16816(Cr, ah, bl0, bl1);                                           \
    }

#define FRAG_REDUCE(Carr, valout)                                             \
    *(float4*)&red[w * 128 + lane * 4] = *(float4*)(Carr);                    \
    __syncthreads();                                                          \
    float valout = 0.f;                                                       \
    int bb = 0, nn = 0;                                                       \
    if (tid < 256) {                                                          \
        bb = tid >> 3; nn = tid & 7;                                          \
        int mtt = bb >> 4, rt = bb & 15;                                      \
        int ln = (rt & 7) * 4 + (nn >> 1);                                    \
        int rg = ((rt >> 3) & 1) * 2 + (nn & 1);                              \
        _Pragma("unroll")                                                     \
        for (int j = 0; j < 8; j++)                                           \
            valout += red[(2 * j + mtt) * 128 + ln * 4 + rg];                 \
    }

    for (int t = 0; t < T_; t++) {
        const __nv_bfloat16* hH = g_hbH[t & 1];
        const __nv_bfloat16* hL = g_hbL[t & 1];
        const float* xpt_t = g_xpt + (size_t)t * NG_ * B_;
        float Cr[4], Cz[4];

        // ========== pass A: z + r in one staging pass ==========
        stage(0, hH, hL);
        stage(1, hH, hL);
        if (tid < 64)
            CPA16(sptr((u32*)&xps[tid * 4]), xpt_t + (size_t)u0 * B_ + tid * 4);
        else if (tid < 128)
            CPA16(sptr((u32*)&xps[tid * 4]), xpt_t + (size_t)(UN_ + u0) * B_ + (tid - 64) * 4);
        else if (tid < 192)
            CPA16(sptr((u32*)&xps[tid * 4]),
                  xpt_t + (size_t)(2 * UN_ + u0) * B_ + (tid - 128) * 4);
        CPCOMMIT();                                       // G0: c0,c1 + xz,xr,xh
        stage(2, hH, hL); stage(3, hH, hL); CPCOMMIT();   // G1

        Cr[0] = Cr[1] = Cr[2] = Cr[3] = 0.f;
        Cz[0] = Cz[1] = Cz[2] = Cz[3] = 0.f;
        CPWAIT1(); __syncthreads();
        stage(4, hH, hL); stage(5, hH, hL); CPCOMMIT();   // G2
        CHUNK_ZR(0) CHUNK_ZR(1)
        CPWAIT1(); __syncthreads();
        stage(6, hH, hL); stage(7, hH, hL); CPCOMMIT();   // G3
        CHUNK_ZR(2) CHUNK_ZR(3)
        CPWAIT1(); __syncthreads();
        CHUNK_ZR(4) CHUNK_ZR(5)
        CPWAIT0(); __syncthreads();
        CHUNK_ZR(6) CHUNK_ZR(7)
        __syncthreads();

        // r first (critical path), then arrive, then z (overlaps wait)
        {
            FRAG_REDUCE(Cr, val)
            if (tid < 256) {
                float rs = val + xps[256 + nn * 32 + bb];
                float r  = 1.f / (1.f + __expf(-rs));
                float rh = r * hown[nn * 32 + bb];
                unsigned short hi = bfu(rh);
                g_rbH[bb * UN_ + u0 + nn] = *(__nv_bfloat16*)&hi;
                unsigned short lo = bfu(rh - ubf(hi));
                g_rbL[bb * UN_ + u0 + nn] = *(__nv_bfloat16*)&lo;
                __threadfence();
            }
        }
        g_arrive(&g_s1);
        {
            FRAG_REDUCE(Cz, val)
            if (tid < 256) {
                float zs = val + xps[nn * 32 + bb];
                z_s[nn * 32 + bb] = 1.f / (1.f + __expf(-zs));
            }
        }
        g_wait(&g_s1, (unsigned)NBLK * (t + 1));

        // ========== pass B: hcand + hn ==========
        stage(0, g_rbH, g_rbL);
        stage(1, g_rbH, g_rbL); CPCOMMIT();               // G0
        stage(2, g_rbH, g_rbL); stage(3, g_rbH, g_rbL); CPCOMMIT();   // G1

        Cr[0] = Cr[1] = Cr[2] = Cr[3] = 0.f;
        CPWAIT1(); __syncthreads();
        stage(4, g_rbH, g_rbL); stage(5, g_rbH, g_rbL); CPCOMMIT();   // G2
        CHUNK_H(0) CHUNK_H(1)
        CPWAIT1(); __syncthreads();
        stage(6, g_rbH, g_rbL); stage(7, g_rbH, g_rbL); CPCOMMIT();   // G3
        CHUNK_H(2) CHUNK_H(3)
        CPWAIT1(); __syncthreads();
        CHUNK_H(4) CHUNK_H(5)
        CPWAIT0(); __syncthreads();
        CHUNK_H(6) CHUNK_H(7)
        __syncthreads();

        {
            FRAG_REDUCE(Cr, val)
            if (tid < 256) {
                float hc = tanhf(val + xps[512 + nn * 32 + bb]);
                float z  = z_s[nn * 32 + bb];
                float ho = hown[nn * 32 + bb];
                float hn = z * ho + (1.f - z) * hc;
                hown[nn * 32 + bb] = hn;
                out[((size_t)bb * T_ + t) * UN_ + u0 + nn] = hn;
                unsigned short hi = bfu(hn);
                g_hbH[(t + 1) & 1][bb * UN_ + u0 + nn] = *(__nv_bfloat16*)&hi;
                unsigned short lo = bfu(hn - ubf(hi));
                g_hbL[(t + 1) & 1][bb * UN_ + u0 + nn] = *(__nv_bfloat16*)&lo;
                if (t == T_ - 1)
                    g_hTf[0][(u0 + nn) * B_ + bb] = hn;
                __threadfence();
            }
        }
        g_arrive(&g_s2);
        g_wait(&g_s2, (unsigned)NBLK * (t + 1));
    }

    // final hidden state hT
    if (bid < 64) {
        int i = bid * 512 + tid;
        int u = i >> 5, b = i & 31;
        out[(size_t)M_ * UN_ + (size_t)b * UN_ + u] = __ldcg(&g_hTf[0][i]);
    }
#undef CHUNK_ZR
#undef CHUNK_H
#undef FRAG_REDUCE
}

// ---------------- launcher ----------------
extern "C" void kernel_launch(void* const* d_in, const int* in_sizes, int n_in,
                              void* d_out, int out_size) {
    const float* x  = (const float*)d_in[0];
    const float* W  = (const float*)d_in[1];
    const float* U  = (const float*)d_in[2];
    const float* b  = (const float*)d_in[3];
    const float* h0 = (const float*)d_in[4];
    float* out = (float*)d_out;

    static bool attr_done = false;
    if (!attr_done) {
        cudaFuncSetAttribute(k_gru, cudaFuncAttributeMaxDynamicSharedMemorySize,
                             SMTOT * 4);
        cudaFuncSetAttribute(k_gemm_mma, cudaFuncAttributeMaxDynamicSharedMemorySize,
                             2 * GSM_BUF * sizeof(__nv_bfloat16));
        attr_done = true;
    }

    k_prep<<<NBLK, 256>>>(b, h0);
    k_split<<<16384 + 3072, 256>>>(x, W);
    {
        dim3 grid(NG_ / 128, M_ / 128);
        k_gemm_mma<<<grid, 256, 2 * GSM_BUF * sizeof(__nv_bfloat16)>>>();
    }
    k_gru<<<NBLK, 512, SMTOT * 4>>>(U, out);
}